// round 5
// baseline (speedup 1.0000x reference)
#include <cuda_runtime.h>
#include <cstdint>

// Problem dims
#define TS 512
#define BB 64
#define ID 512
#define HD 512
#define GD 2048

// Scan config
#define NBLK 128
#define NTH  512
#define CHK  128                    // k per chunk
#define HSS  68                     // padded h row stride (floats)
#define US_FLOATS (512 * 16)        // 8192
#define BUF_FLOATS (CHK * HSS)      // 8704
#define RED_U64 (8 * 7 * 64)        // [j][split][col]
#define SCAN_SMEM ((US_FLOATS + 2 * BUF_FLOATS) * 4 + RED_U64 * 8)  // 131072

// Static scratch
__device__ float g_xw[TS * BB * GD];   // [t][hc][b][gate]
__device__ float g_h[2][HD * BB];      // [hc][b], double buffered
__device__ unsigned g_grp[16 * 32];    // group counters, 128B apart
__device__ unsigned g_root = 0;
__device__ unsigned g_gen = 0;

// ---------------- packed fp32x2 helpers ----------------
static __device__ __forceinline__ uint64_t pack2(float x, float y) {
    uint64_t d; asm("mov.b64 %0,{%1,%2};" : "=l"(d) : "f"(x), "f"(y)); return d;
}
static __device__ __forceinline__ void unpack2(uint64_t d, float& x, float& y) {
    asm("mov.b64 {%0,%1},%2;" : "=f"(x), "=f"(y) : "l"(d));
}
static __device__ __forceinline__ uint64_t ffma2(uint64_t a, uint64_t b, uint64_t c) {
    uint64_t d; asm("fma.rn.f32x2 %0,%1,%2,%3;" : "=l"(d) : "l"(a), "l"(b), "l"(c)); return d;
}
static __device__ __forceinline__ uint64_t fadd2(uint64_t a, uint64_t b) {
    uint64_t d; asm("add.rn.f32x2 %0,%1,%2;" : "=l"(d) : "l"(a), "l"(b)); return d;
}
static __device__ __forceinline__ void cpasync16(uint32_t dst, const void* src) {
    asm volatile("cp.async.cg.shared.global [%0], [%1], 16;" :: "r"(dst), "l"(src));
}
static __device__ __forceinline__ uint32_t smem_u32(const void* p) {
    uint32_t a;
    asm("{ .reg .u64 t; cvta.to.shared.u64 t, %1; cvt.u32.u64 %0, t; }" : "=r"(a) : "l"(p));
    return a;
}

// ---------------------------------------------------------------------------
// Kernel 1: xW = x @ W + b  (UNCHANGED from passing version)
// ---------------------------------------------------------------------------
__global__ void __launch_bounds__(256, 2) gemm_xw_kernel(
    const float* __restrict__ A,
    const float* __restrict__ Bw,
    const float* __restrict__ bias)
{
    __shared__ float As[8][128];
    __shared__ float Bs[8][128];

    const int tid = threadIdx.x;
    const int m0 = blockIdx.y * 128;
    const int n0 = blockIdx.x * 128;

    const int a_row = tid >> 1;
    const int a_col = (tid & 1) * 4;
    const int b_row = tid >> 5;
    const int b_col = (tid & 31) * 4;
    const int tx = (tid & 15) * 8;
    const int ty = (tid >> 4) * 8;

    uint64_t acc[8][4];
    {
        float4 bA = *(const float4*)&bias[n0 + tx];
        float4 bB = *(const float4*)&bias[n0 + tx + 4];
        uint64_t b2[4] = { pack2(bA.x, bA.y), pack2(bA.z, bA.w),
                           pack2(bB.x, bB.y), pack2(bB.z, bB.w) };
#pragma unroll
        for (int i = 0; i < 8; i++)
#pragma unroll
            for (int j = 0; j < 4; j++) acc[i][j] = b2[j];
    }

    const float* Aptr = A + (m0 + a_row) * ID + a_col;
    const float* Bptr = Bw + b_row * GD + n0 + b_col;

    for (int k0 = 0; k0 < ID; k0 += 8) {
        float4 av = *(const float4*)(Aptr + k0);
        float4 bv = *(const float4*)(Bptr + (size_t)k0 * GD);
        __syncthreads();
        As[a_col + 0][a_row] = av.x;
        As[a_col + 1][a_row] = av.y;
        As[a_col + 2][a_row] = av.z;
        As[a_col + 3][a_row] = av.w;
        *(float4*)&Bs[b_row][b_col] = bv;
        __syncthreads();
#pragma unroll
        for (int k = 0; k < 8; k++) {
            float4 a0 = *(const float4*)&As[k][ty];
            float4 a1 = *(const float4*)&As[k][ty + 4];
            const uint64_t* bp2 = (const uint64_t*)&Bs[k][tx];
            uint64_t bf0 = bp2[0], bf1 = bp2[1], bf2 = bp2[2], bf3 = bp2[3];
            uint64_t ad[8] = { pack2(a0.x, a0.x), pack2(a0.y, a0.y),
                               pack2(a0.z, a0.z), pack2(a0.w, a0.w),
                               pack2(a1.x, a1.x), pack2(a1.y, a1.y),
                               pack2(a1.z, a1.z), pack2(a1.w, a1.w) };
#pragma unroll
            for (int i = 0; i < 8; i++) {
                acc[i][0] = ffma2(ad[i], bf0, acc[i][0]);
                acc[i][1] = ffma2(ad[i], bf1, acc[i][1]);
                acc[i][2] = ffma2(ad[i], bf2, acc[i][2]);
                acc[i][3] = ffma2(ad[i], bf3, acc[i][3]);
            }
        }
    }

#pragma unroll
    for (int i = 0; i < 8; i++) {
        int m = m0 + ty + i;
        int t = m >> 6;
        int b = m & 63;
        float* base = g_xw + (size_t)t * (BB * GD) + b * 4;
#pragma unroll
        for (int j = 0; j < 4; j++) {
            float lo, hi;
            unpack2(acc[i][j], lo, hi);
            int n = n0 + tx + 2 * j;
            int gate = n >> 9;
            int hc = n & 511;
            base[hc * 256 + gate] = lo;
            base[(hc + 1) * 256 + gate] = hi;
        }
    }
}

// ---------------------------------------------------------------------------
// Tree grid barrier: 16 groups x 8 blocks, monotonic counters.
// n = lifetime barrier index (base read from g_gen at kernel start + local t).
// ---------------------------------------------------------------------------
static __device__ __forceinline__ void grid_barrier(unsigned n, int bid)
{
    __syncthreads();
    if (threadIdx.x == 0) {
        __threadfence();
        int g = bid >> 3;
        if (atomicAdd(&g_grp[g * 32], 1u) == 8u * n + 7u) {
            if (atomicAdd(&g_root, 1u) == 16u * n + 15u) {
                __threadfence();
                atomicAdd(&g_gen, 1u);          // g_gen becomes n+1
            }
        }
        while (*(volatile unsigned*)&g_gen < n + 1u) { }
        __threadfence();
    }
    __syncthreads();
}

// ---------------------------------------------------------------------------
// Kernel 2: persistent scan. 128 blocks x 512 threads.
// Thread (bp 0..31, hg 0..1, kh 0..7): outputs (hc0=4bid+2hg+{0,1}, b={2bp,2bp+1}),
// k-slice = 16 k per 128-k chunk (kh*16..kh*16+16), 4 chunks per step.
// Chunks double-buffered via cp.async; k-split partials reduced in smem;
// hprev carried in registers across steps.
// ---------------------------------------------------------------------------
__global__ void __launch_bounds__(NTH, 1) lstm_scan_kernel(
    const float* __restrict__ a0,   // [64][512]
    const float* __restrict__ U,    // [512][2048]
    float* __restrict__ out)        // [512][64][512]
{
    extern __shared__ float sm[];
    float* Us = sm;                                  // [512][16] hl-major, gate inner
    float* buf0 = sm + US_FLOATS;                    // chunk buffers [128][HSS]
    float* buf1 = buf0 + BUF_FLOATS;
    uint64_t* red = (uint64_t*)(buf1 + BUF_FLOATS);  // [8][7][64]

    const int tid = threadIdx.x;
    const int bid = blockIdx.x;

    const unsigned n0 = *(volatile unsigned*)&g_gen; // lifetime barrier base

    for (int i = tid; i < US_FLOATS; i += NTH) {
        int k = i >> 4, c = i & 15, hl = c >> 2, g = c & 3;
        Us[i] = U[(size_t)k * GD + g * HD + bid * 4 + hl];
    }

    const int bp = tid & 31;
    const int hg = (tid >> 5) & 1;
    const int kh = tid >> 6;                // 0..7
    const int b0 = bp * 2;
    const int hc0 = bid * 4 + hg * 2;

    float* bufs[2] = { buf0, buf1 };
    uint32_t bufa[2] = { smem_u32(buf0), smem_u32(buf1) };

    // persistent previous-h registers (kh==0 threads only)
    float hprev[4];
    if (kh == 0) {
        hprev[0] = a0[b0 * HD + hc0];
        hprev[1] = a0[(b0 + 1) * HD + hc0];
        hprev[2] = a0[b0 * HD + hc0 + 1];
        hprev[3] = a0[(b0 + 1) * HD + hc0 + 1];
    }

    for (int t = 0; t < TS; t++) {
        const float* hsrc = g_h[(t ^ 1) & 1];

        // accumulators (xW folded in on kh==0, issued immediately after barrier)
        uint64_t A000, A001, A010, A011, A100, A101, A110, A111;
        if (kh == 0) {
            const float* xwt = g_xw + (size_t)t * (BB * GD) + hc0 * 256 + b0 * 4;
            float4 x00 = *(const float4*)(xwt);
            float4 x01 = *(const float4*)(xwt + 4);
            float4 x10 = *(const float4*)(xwt + 256);
            float4 x11 = *(const float4*)(xwt + 260);
            A000 = pack2(x00.x, x00.y); A010 = pack2(x00.z, x00.w);
            A001 = pack2(x01.x, x01.y); A011 = pack2(x01.z, x01.w);
            A100 = pack2(x10.x, x10.y); A110 = pack2(x10.z, x10.w);
            A101 = pack2(x11.x, x11.y); A111 = pack2(x11.z, x11.w);
        } else {
            A000 = A001 = A010 = A011 = A100 = A101 = A110 = A111 = 0ULL;
        }

#define FMA_CHUNK(c, bf)                                                     \
        {                                                                    \
            const float* up = Us + ((c) * CHK + kh * 16) * 16 + hg * 8;      \
            const float* hp = (bf) + (kh * 16) * HSS + b0;                   \
            _Pragma("unroll")                                                \
            for (int i = 0; i < 16; i++) {                                   \
                float2 hv = *(const float2*)(hp + i * HSS);                  \
                const uint64_t* uq = (const uint64_t*)(up + i * 16);         \
                uint64_t u0a = uq[0], u0b = uq[1], u1a = uq[2], u1b = uq[3]; \
                uint64_t h0 = pack2(hv.x, hv.x);                             \
                uint64_t h1 = pack2(hv.y, hv.y);                             \
                A000 = ffma2(u0a, h0, A000);                                 \
                A010 = ffma2(u0b, h0, A010);                                 \
                A001 = ffma2(u0a, h1, A001);                                 \
                A011 = ffma2(u0b, h1, A011);                                 \
                A100 = ffma2(u1a, h0, A100);                                 \
                A110 = ffma2(u1b, h0, A110);                                 \
                A101 = ffma2(u1a, h1, A101);                                 \
                A111 = ffma2(u1b, h1, A111);                                 \
            }                                                                \
        }

        if (t == 0) {
            // one-time a0 transpose staging (b-major -> [k][b]), chunked
#pragma unroll 1
            for (int c = 0; c < 4; c++) {
                __syncthreads();
                float* bf = bufs[c & 1];
#pragma unroll
                for (int j = 0; j < 16; j++) {
                    int e = tid + j * NTH;
                    int bb = e >> 7, kk = e & 127;
                    bf[kk * HSS + bb] = a0[bb * HD + c * CHK + kk];
                }
                __syncthreads();
                FMA_CHUNK(c, bufs[c & 1]);
            }
        } else {
            // issue chunks 0 and 1
#pragma unroll
            for (int c0 = 0; c0 < 2; c0++) {
                const float* src = hsrc + c0 * (CHK * BB);
#pragma unroll
                for (int j = 0; j < 4; j++) {
                    int e = (tid + j * NTH) * 4;
                    int kk = e >> 6, bb = e & 63;
                    cpasync16(bufa[c0] + (kk * HSS + bb) * 4, src + e);
                }
                asm volatile("cp.async.commit_group;");
            }
#pragma unroll 1
            for (int c = 0; c < 4; c++) {
                if (c < 3) asm volatile("cp.async.wait_group 1;");
                else       asm volatile("cp.async.wait_group 0;");
                __syncthreads();
                FMA_CHUNK(c, bufs[c & 1]);
                if (c < 2) {
                    __syncthreads();           // buf[c&1] fully consumed
                    const float* src = hsrc + (c + 2) * (CHK * BB);
#pragma unroll
                    for (int j = 0; j < 4; j++) {
                        int e = (tid + j * NTH) * 4;
                        int kk = e >> 6, bb = e & 63;
                        cpasync16(bufa[c & 1] + (kk * HSS + bb) * 4, src + e);
                    }
                    asm volatile("cp.async.commit_group;");
                }
            }
        }

        // k-split reduction: red[j][kh-1][col], conflict-free per j
        if (kh != 0) {
            uint64_t* rp = red + (kh - 1) * 64 + (tid & 63);
            rp[0 * 448] = A000; rp[1 * 448] = A001;
            rp[2 * 448] = A010; rp[3 * 448] = A011;
            rp[4 * 448] = A100; rp[5 * 448] = A101;
            rp[6 * 448] = A110; rp[7 * 448] = A111;
        }
        __syncthreads();
        if (kh == 0) {
#pragma unroll
            for (int p = 0; p < 7; p++) {
                const uint64_t* q = red + p * 64 + tid;
                A000 = fadd2(A000, q[0 * 448]); A001 = fadd2(A001, q[1 * 448]);
                A010 = fadd2(A010, q[2 * 448]); A011 = fadd2(A011, q[3 * 448]);
                A100 = fadd2(A100, q[4 * 448]); A101 = fadd2(A101, q[5 * 448]);
                A110 = fadd2(A110, q[6 * 448]); A111 = fadd2(A111, q[7 * 448]);
            }

            float av[4];
            uint64_t P01[4] = { A000, A001, A100, A101 };
            uint64_t P23[4] = { A010, A011, A110, A111 };
#pragma unroll
            for (int o = 0; o < 4; o++) {
                float xu, xf, xo, xc;
                unpack2(P01[o], xu, xf);
                unpack2(P23[o], xo, xc);
                float su = 1.f / (1.f + __expf(-xu));
                float sf = 1.f / (1.f + __expf(-xf));
                float so = 1.f / (1.f + __expf(-xo));
                float cd = tanhf(xc);
                float cv = su * cd + sf * hprev[o];
                av[o] = so * tanhf(cv);
                hprev[o] = av[o];
            }

            float* ht = g_h[t & 1];
            *(float2*)&ht[hc0 * BB + b0]       = make_float2(av[0], av[1]);
            *(float2*)&ht[(hc0 + 1) * BB + b0] = make_float2(av[2], av[3]);

            float* ot = out + (size_t)t * (BB * HD);
            *(float2*)&ot[b0 * HD + hc0]       = make_float2(av[0], av[2]);
            *(float2*)&ot[(b0 + 1) * HD + hc0] = make_float2(av[1], av[3]);
        }

        if (t != TS - 1) grid_barrier(n0 + (unsigned)t, bid);
#undef FMA_CHUNK
    }
}

// ---------------------------------------------------------------------------
extern "C" void kernel_launch(void* const* d_in, const int* in_sizes, int n_in,
                              void* d_out, int out_size)
{
    const float* x   = (const float*)d_in[0];
    const float* a0  = (const float*)d_in[1];
    const float* W   = (const float*)d_in[2];
    const float* U   = (const float*)d_in[3];
    const float* bia = (const float*)d_in[4];
    float* out = (float*)d_out;

    cudaFuncSetAttribute(lstm_scan_kernel,
                         cudaFuncAttributeMaxDynamicSharedMemorySize, SCAN_SMEM);

    gemm_xw_kernel<<<dim3(GD / 128, (TS * BB) / 128), 256>>>(x, W, bia);
    lstm_scan_kernel<<<NBLK, NTH, SCAN_SMEM>>>(a0, U, out);
}